// round 6
// baseline (speedup 1.0000x reference)
#include <cuda_runtime.h>
#include <stdint.h>

#define BATCH 64
#define NA    8400
#define NC    80
#define HF_   160
#define WF_   160
#define KTOP  300

#define MULrn(a,b) __fmul_rn((a),(b))
#define ADDrn(a,b) __fadd_rn((a),(b))
#define SUBrn(a,b) __fsub_rn((a),(b))
#define DIVrn(a,b) __fdiv_rn((a),(b))

// Scratch (allocation-free rule: __device__ globals)
__device__ float g_score[BATCH * NA];
__device__ int   g_cls[BATCH * NA];
__device__ float g_beta[BATCH * NA];

// XLA EmitFastTanh (Eigen rational), no fma contraction, clamp +-7.90531110763549805,
// passthrough for |x| < 4e-4.
__device__ __forceinline__ float tanh_xla(float x) {
    const float kMax = 7.90531110763549805f;
    float xc = fmaxf(-kMax, fminf(x, kMax));
    float x2 = MULrn(xc, xc);
    float p = -2.76076847742355e-16f;
    p = ADDrn(MULrn(x2, p),  2.00018790482477e-13f);
    p = ADDrn(MULrn(x2, p), -8.60467152213735e-11f);
    p = ADDrn(MULrn(x2, p),  5.12229709037114e-08f);
    p = ADDrn(MULrn(x2, p),  1.48572235717979e-05f);
    p = ADDrn(MULrn(x2, p),  6.37261928875436e-04f);
    p = ADDrn(MULrn(x2, p),  4.89352455891786e-03f);
    float num = MULrn(xc, p);
    float q = 1.19825839466702e-06f;
    q = ADDrn(MULrn(x2, q), 1.18534705686654e-04f);
    q = ADDrn(MULrn(x2, q), 2.26843463243900e-03f);
    q = ADDrn(MULrn(x2, q), 4.89352518554385e-03f);
    float t = DIVrn(num, q);
    return (fabsf(x) < 0.0004f) ? x : t;
}

// XLA logistic: 0.5 + 0.5 * tanh(0.5 * x)  (all pow-2 scalings: exact)
__device__ __forceinline__ float sigmoid_xla(float x) {
    float th = tanh_xla(MULrn(0.5f, x));
    return ADDrn(0.5f, MULrn(0.5f, th));
}

// 4 threads per anchor. Each thread holds 20 class logits in registers.
__global__ void __launch_bounds__(256) score_kernel(
        const float4* __restrict__ boxes,
        const float*  __restrict__ obj,
        const float4* __restrict__ cls,
        const float*  __restrict__ field) {
    int gt = blockIdx.x * 256 + threadIdx.x;
    int anchor = gt >> 2;
    int sub = gt & 3;
    int b = anchor / NA;

    // issue cls loads early: 5 float4 per thread, interleaved across the 4 lanes
    const float4* cp = cls + (size_t)anchor * (NC / 4);
    float4 v[5];
#pragma unroll
    for (int q = 0; q < 5; q++) v[q] = __ldg(cp + sub + 4 * q);

    float4 bx = __ldg(boxes + anchor);

    // --- pooling + calibration (lane 0 of each 4-group, XLA-bit-exact) ---
    float bs = 0.0f;
    if (sub == 0) {
        const float* f = field + (size_t)b * (HF_ * WF_);
        float x1 = bx.x, y1 = bx.y, x2 = bx.z, y2 = bx.w;
        float dx = SUBrn(x2, x1), dy = SUBrn(y2, y1);
        float fu[3], fv[3];
        int u0[3], u1[3], v0[3], v1[3];
#pragma unroll
        for (int j = 0; j < 3; j++) {
            // XLA simplifier: (j+0.5)/3 -> (j+0.5) * rn(1/3)  (t[2] = 0x3F555556)
            float t  = MULrn((float)j + 0.5f, 1.0f / 3.0f);
            float xs = ADDrn(x1, MULrn(t, dx));
            float ys = ADDrn(y1, MULrn(t, dy));
            float u = fminf(fmaxf(SUBrn(MULrn(xs, 0.25f), 0.5f), 0.0f), 159.0f);
            float vv = fminf(fmaxf(SUBrn(MULrn(ys, 0.25f), 0.5f), 0.0f), 159.0f);
            float u0f = floorf(u), v0f = floorf(vv);
            fu[j] = SUBrn(u, u0f); fv[j] = SUBrn(vv, v0f);
            u0[j] = (int)u0f; v0[j] = (int)v0f;
            u1[j] = min(u0[j] + 1, WF_ - 1);
            v1[j] = min(v0[j] + 1, HF_ - 1);
        }
        float e[9];
#pragma unroll
        for (int jy = 0; jy < 3; jy++) {
            int r0 = v0[jy] * WF_, r1 = v1[jy] * WF_;
            float wv = fv[jy], omv = SUBrn(1.0f, fv[jy]);
#pragma unroll
            for (int jx = 0; jx < 3; jx++) {
                float wu = fu[jx], omu = SUBrn(1.0f, fu[jx]);
                float f00 = __ldg(f + r0 + u0[jx]);
                float f01 = __ldg(f + r0 + u1[jx]);
                float f10 = __ldg(f + r1 + u0[jx]);
                float f11 = __ldg(f + r1 + u1[jx]);
                float t1 = MULrn(MULrn(f00, omv), omu);
                float t2 = MULrn(MULrn(f01, omv), wu);
                float t3 = MULrn(MULrn(f10, wv), omu);
                float t4 = MULrn(MULrn(f11, wv), wu);
                e[jy * 3 + jx] = ADDrn(ADDrn(ADDrn(t1, t2), t3), t4);
            }
        }
        // XLA multi-row reduction: 16-lane shfl tree (offsets 8,4,2,1), lanes 9..15 = 0.
        // sum = (((e0+e8)+e4)+(e2+e6)) + ((e1+e5)+(e3+e7))
        float s_left  = ADDrn(ADDrn(ADDrn(e[0], e[8]), e[4]), ADDrn(e[2], e[6]));
        float s_right = ADDrn(ADDrn(e[1], e[5]), ADDrn(e[3], e[7]));
        float ssum    = ADDrn(s_left, s_right);
        // mean: /9 -> * rn(1/9)
        float beta = MULrn(ssum, 1.0f / 9.0f);
        float w = fmaxf(dx, 0.0f), h = fmaxf(dy, 0.0f);
        // /409600 -> * rn(1/409600)
        float area = MULrn(MULrn(w, h), 1.0f / 409600.0f);
        float small = (area < 0.01f) ? 1.0f : 0.0f;
        bs = MULrn(beta, ADDrn(1.0f, MULrn(0.5f, small)));
    }
    bs = __shfl_sync(0xffffffffu, bs, 0, 4);
    float halfbs = MULrn(0.5f, bs);   // exact (pow-2 scale)

    // --- max logit across the anchor's 80 classes ---
    float m_loc = -3.0e38f;
#pragma unroll
    for (int q = 0; q < 5; q++)
        m_loc = fmaxf(m_loc, fmaxf(fmaxf(v[q].x, v[q].y), fmaxf(v[q].z, v[q].w)));
    float m1 = m_loc;
#pragma unroll
    for (int off = 1; off < 4; off <<= 1)
        m1 = fmaxf(m1, __shfl_xor_sync(0xffffffffu, m1, off, 4));

    // --- exact argmax over sigmoid(cal_cls): only candidates within the
    //     sigmoid ulp-plateau window of m1 need the exact sigmoid ---
    float thrW = m1 - 3e-4f;
    float bestS = -1.0f; int bestI = 0x7fffffff;
    if (m_loc > thrW) {
#pragma unroll
        for (int q = 0; q < 5; q++) {
            float ev[4] = {v[q].x, v[q].y, v[q].z, v[q].w};
#pragma unroll
            for (int r = 0; r < 4; r++) {
                if (ev[r] > thrW) {
                    int ci = (sub + 4 * q) * 4 + r;
                    float sgv = sigmoid_xla(SUBrn(ev[r], halfbs));
                    if (sgv > bestS || (sgv == bestS && ci < bestI)) { bestS = sgv; bestI = ci; }
                }
            }
        }
    }
#pragma unroll
    for (int off = 1; off < 4; off <<= 1) {
        float os = __shfl_xor_sync(0xffffffffu, bestS, off, 4);
        int   oi = __shfl_xor_sync(0xffffffffu, bestI, off, 4);
        if (os > bestS || (os == bestS && oi < bestI)) { bestS = os; bestI = oi; }
    }

    if (sub == 0) {
        float so = sigmoid_xla(SUBrn(__ldg(obj + anchor), bs));  // LOBJ=1.0 exact
        float comb = MULrn(so, bestS);
        g_score[anchor] = (comb >= 0.25f) ? comb : 0.0f;
        g_cls[anchor]   = bestI;
        g_beta[anchor]  = bs;
    }
}

// One block per batch row. Radix-select pivot for rank Kv, gather, bitonic sort.
__global__ void topk_kernel(const float4* __restrict__ boxes, float* __restrict__ out) {
    __shared__ uint32_t skey[NA];
    __shared__ unsigned long long sbuf[1024];
    __shared__ uint32_t hist[256];
    __shared__ int s_digit, s_rem, s_cnt, s_valid;

    int b = blockIdx.x;
    int tid = threadIdx.x, nt = blockDim.x;
    const float* sc = g_score + (size_t)b * NA;

    if (tid == 0) { s_valid = 0; s_cnt = 0; }
    __syncthreads();

    int vcnt = 0;
    for (int i = tid; i < NA; i += nt) {
        uint32_t k = __float_as_uint(sc[i]);
        skey[i] = k;
        if (k) vcnt++;
    }
    atomicAdd(&s_valid, vcnt);
    __syncthreads();

    int Kv = min(s_valid, KTOP);

    uint32_t prefix = 0;
    int remaining = Kv;
    if (Kv > 0) {
        for (int shift = 24; shift >= 0; shift -= 8) {
            for (int i = tid; i < 256; i += nt) hist[i] = 0;
            __syncthreads();
            uint32_t hm = (shift == 24) ? 0u : (0xFFFFFFFFu << (shift + 8));
            for (int i = tid; i < NA; i += nt) {
                uint32_t k = skey[i];
                if ((k & hm) == prefix) atomicAdd(&hist[(k >> shift) & 0xFF], 1);
            }
            __syncthreads();
            if (tid == 0) {
                int cum = 0, d = 255;
                for (; d > 0; d--) {
                    int c = (int)hist[d];
                    if (cum + c >= remaining) break;
                    cum += c;
                }
                s_digit = d;
                s_rem = remaining - cum;
            }
            __syncthreads();
            prefix |= ((uint32_t)s_digit) << shift;
            remaining = s_rem;
            __syncthreads();
        }

        // gather keys >= pivot (ties included; sort breaks ties by ascending index)
        for (int i = tid; i < NA; i += nt) {
            uint32_t k = skey[i];
            if (k >= prefix && k != 0) {
                int p = atomicAdd(&s_cnt, 1);
                if (p < 1024)
                    sbuf[p] = ((unsigned long long)k << 32) | (uint32_t)(~(uint32_t)i);
            }
        }
    }
    __syncthreads();

    int n = min(s_cnt, 1024);
    for (int i = tid; i < 1024; i += nt)
        if (i >= n) sbuf[i] = 0ULL;
    __syncthreads();

    // bitonic sort descending (composite key: ties -> ascending anchor index)
    for (int k2 = 2; k2 <= 1024; k2 <<= 1) {
        for (int j = k2 >> 1; j > 0; j >>= 1) {
            for (int i = tid; i < 1024; i += nt) {
                int p = i ^ j;
                if (p > i) {
                    unsigned long long a = sbuf[i], c = sbuf[p];
                    bool desc = ((i & k2) == 0);
                    if (desc ? (a < c) : (a > c)) { sbuf[i] = c; sbuf[p] = a; }
                }
            }
            __syncthreads();
        }
    }

    // output layout: boxes[B][K][4] | scores[B][K] | classes[B][K] | suspicion[B][K] | valid[B][K]
    float* ob = out;
    float* os = out + (size_t)BATCH * KTOP * 4;
    float* oc = os + (size_t)BATCH * KTOP;
    float* ou = oc + (size_t)BATCH * KTOP;
    float* ov = ou + (size_t)BATCH * KTOP;

    for (int k = tid; k < KTOP; k += nt) {
        float4 bo = make_float4(0.f, 0.f, 0.f, 0.f);
        float scv = 0.f, cl = 0.f, su = 0.f, va = 0.f;
        if (k < Kv) {
            unsigned long long c = sbuf[k];
            uint32_t key = (uint32_t)(c >> 32);
            int ai = (int)(~(uint32_t)c);
            int gi = b * NA + ai;
            bo  = boxes[gi];
            scv = __uint_as_float(key);
            cl  = (float)g_cls[gi];
            su  = g_beta[gi];
            va  = 1.0f;
        }
        ((float4*)ob)[(size_t)b * KTOP + k] = bo;
        os[(size_t)b * KTOP + k] = scv;
        oc[(size_t)b * KTOP + k] = cl;
        ou[(size_t)b * KTOP + k] = su;
        ov[(size_t)b * KTOP + k] = va;
    }
}

extern "C" void kernel_launch(void* const* d_in, const int* in_sizes, int n_in,
                              void* d_out, int out_size) {
    const float* boxes = nullptr;
    const float* obj   = nullptr;
    const float* cls   = nullptr;
    const float* field = nullptr;
    for (int i = 0; i < n_in; i++) {
        int s = in_sizes[i];
        if      (s == BATCH * NA * 4)      boxes = (const float*)d_in[i];
        else if (s == BATCH * NA)          obj   = (const float*)d_in[i];
        else if (s == BATCH * NA * NC)     cls   = (const float*)d_in[i];
        else if (s == BATCH * HF_ * WF_)   field = (const float*)d_in[i];
    }
    int total_threads = BATCH * NA * 4;
    score_kernel<<<total_threads / 256, 256>>>((const float4*)boxes, obj,
                                               (const float4*)cls, field);
    topk_kernel<<<BATCH, 256>>>((const float4*)boxes, (float*)d_out);
}

// round 7
// speedup vs baseline: 1.6820x; 1.6820x over previous
#include <cuda_runtime.h>
#include <stdint.h>

#define BATCH 64
#define NA    8400
#define NC    80
#define HF_   160
#define WF_   160
#define KTOP  300

#define MULrn(a,b) __fmul_rn((a),(b))
#define ADDrn(a,b) __fadd_rn((a),(b))
#define SUBrn(a,b) __fsub_rn((a),(b))
#define DIVrn(a,b) __fdiv_rn((a),(b))

// Scratch (allocation-free rule: __device__ globals)
__device__ float g_score[BATCH * NA];
__device__ int   g_cls[BATCH * NA];
__device__ float g_beta[BATCH * NA];

// XLA EmitFastTanh (Eigen rational), no fma contraction, clamp +-7.90531110763549805,
// passthrough for |x| < 4e-4.
__device__ __forceinline__ float tanh_xla(float x) {
    const float kMax = 7.90531110763549805f;
    float xc = fmaxf(-kMax, fminf(x, kMax));
    float x2 = MULrn(xc, xc);
    float p = -2.76076847742355e-16f;
    p = ADDrn(MULrn(x2, p),  2.00018790482477e-13f);
    p = ADDrn(MULrn(x2, p), -8.60467152213735e-11f);
    p = ADDrn(MULrn(x2, p),  5.12229709037114e-08f);
    p = ADDrn(MULrn(x2, p),  1.48572235717979e-05f);
    p = ADDrn(MULrn(x2, p),  6.37261928875436e-04f);
    p = ADDrn(MULrn(x2, p),  4.89352455891786e-03f);
    float num = MULrn(xc, p);
    float q = 1.19825839466702e-06f;
    q = ADDrn(MULrn(x2, q), 1.18534705686654e-04f);
    q = ADDrn(MULrn(x2, q), 2.26843463243900e-03f);
    q = ADDrn(MULrn(x2, q), 4.89352518554385e-03f);
    float t = DIVrn(num, q);
    return (fabsf(x) < 0.0004f) ? x : t;
}

// XLA logistic: 0.5 + 0.5 * tanh(0.5 * x)  (pow-2 scalings: exact)
__device__ __forceinline__ float sigmoid_xla(float x) {
    float th = tanh_xla(MULrn(0.5f, x));
    return ADDrn(0.5f, MULrn(0.5f, th));
}

// ---------------- Kernel 1: box pooling (1 thread / anchor) ----------------
__global__ void __launch_bounds__(256) pool_kernel(
        const float4* __restrict__ boxes,
        const float*  __restrict__ field) {
    int anchor = blockIdx.x * 256 + threadIdx.x;   // exactly BATCH*NA threads
    int b = anchor / NA;

    float4 bx = __ldg(boxes + anchor);
    const float* f = field + (size_t)b * (HF_ * WF_);
    float x1 = bx.x, y1 = bx.y, x2 = bx.z, y2 = bx.w;
    float dx = SUBrn(x2, x1), dy = SUBrn(y2, y1);
    float fu[3], fv[3];
    int u0[3], u1[3], v0[3], v1[3];
#pragma unroll
    for (int j = 0; j < 3; j++) {
        // XLA simplifier: (j+0.5)/3 -> (j+0.5) * rn(1/3)
        float t  = MULrn((float)j + 0.5f, 1.0f / 3.0f);
        float xs = ADDrn(x1, MULrn(t, dx));
        float ys = ADDrn(y1, MULrn(t, dy));
        float u  = fminf(fmaxf(SUBrn(MULrn(xs, 0.25f), 0.5f), 0.0f), 159.0f);
        float vv = fminf(fmaxf(SUBrn(MULrn(ys, 0.25f), 0.5f), 0.0f), 159.0f);
        float u0f = floorf(u), v0f = floorf(vv);
        fu[j] = SUBrn(u, u0f); fv[j] = SUBrn(vv, v0f);
        u0[j] = (int)u0f; v0[j] = (int)v0f;
        u1[j] = min(u0[j] + 1, WF_ - 1);
        v1[j] = min(v0[j] + 1, HF_ - 1);
    }
    float e[9];
#pragma unroll
    for (int jy = 0; jy < 3; jy++) {
        int r0 = v0[jy] * WF_, r1 = v1[jy] * WF_;
        float wv = fv[jy], omv = SUBrn(1.0f, fv[jy]);
#pragma unroll
        for (int jx = 0; jx < 3; jx++) {
            float wu = fu[jx], omu = SUBrn(1.0f, fu[jx]);
            float f00 = __ldg(f + r0 + u0[jx]);
            float f01 = __ldg(f + r0 + u1[jx]);
            float f10 = __ldg(f + r1 + u0[jx]);
            float f11 = __ldg(f + r1 + u1[jx]);
            float t1 = MULrn(MULrn(f00, omv), omu);
            float t2 = MULrn(MULrn(f01, omv), wu);
            float t3 = MULrn(MULrn(f10, wv), omu);
            float t4 = MULrn(MULrn(f11, wv), wu);
            e[jy * 3 + jx] = ADDrn(ADDrn(ADDrn(t1, t2), t3), t4);
        }
    }
    // XLA 16-lane shfl-tree reduce order:
    float s_left  = ADDrn(ADDrn(ADDrn(e[0], e[8]), e[4]), ADDrn(e[2], e[6]));
    float s_right = ADDrn(ADDrn(e[1], e[5]), ADDrn(e[3], e[7]));
    float ssum    = ADDrn(s_left, s_right);
    float beta = MULrn(ssum, 1.0f / 9.0f);            // /9 -> * rn(1/9)
    float w = fmaxf(dx, 0.0f), h = fmaxf(dy, 0.0f);
    float area = MULrn(MULrn(w, h), 1.0f / 409600.0f); // /409600 -> * rn(1/409600)
    float small = (area < 0.01f) ? 1.0f : 0.0f;
    g_beta[anchor] = MULrn(beta, ADDrn(1.0f, MULrn(0.5f, small)));
}

// ---------------- Kernel 2: class scan + calibration (4 threads / anchor) ---
__global__ void __launch_bounds__(256) score_kernel(
        const float*  __restrict__ obj,
        const float4* __restrict__ cls) {
    int gt = blockIdx.x * 256 + threadIdx.x;
    int anchor = gt >> 2;
    int sub = gt & 3;

    const float4* cp = cls + (size_t)anchor * (NC / 4);
    float4 v[5];
#pragma unroll
    for (int q = 0; q < 5; q++) v[q] = __ldg(cp + sub + 4 * q);

    float bs = g_beta[anchor];           // same line for the 4-lane group: broadcast
    float halfbs = MULrn(0.5f, bs);      // exact pow-2 scale

    // max logit across the anchor's 80 classes
    float m_loc = -3.0e38f;
#pragma unroll
    for (int q = 0; q < 5; q++)
        m_loc = fmaxf(m_loc, fmaxf(fmaxf(v[q].x, v[q].y), fmaxf(v[q].z, v[q].w)));
    float m1 = m_loc;
#pragma unroll
    for (int off = 1; off < 4; off <<= 1)
        m1 = fmaxf(m1, __shfl_xor_sync(0xffffffffu, m1, off, 4));

    // exact argmax over sigmoid(cal_cls): only plateau-window candidates
    float thrW = m1 - 3e-4f;
    float bestS = -1.0f; int bestI = 0x7fffffff;
    if (m_loc > thrW) {
#pragma unroll
        for (int q = 0; q < 5; q++) {
            float ev[4] = {v[q].x, v[q].y, v[q].z, v[q].w};
#pragma unroll
            for (int r = 0; r < 4; r++) {
                if (ev[r] > thrW) {
                    int ci = (sub + 4 * q) * 4 + r;
                    float sgv = sigmoid_xla(SUBrn(ev[r], halfbs));
                    if (sgv > bestS || (sgv == bestS && ci < bestI)) { bestS = sgv; bestI = ci; }
                }
            }
        }
    }
#pragma unroll
    for (int off = 1; off < 4; off <<= 1) {
        float os = __shfl_xor_sync(0xffffffffu, bestS, off, 4);
        int   oi = __shfl_xor_sync(0xffffffffu, bestI, off, 4);
        if (os > bestS || (os == bestS && oi < bestI)) { bestS = os; bestI = oi; }
    }

    if (sub == 0) {
        float so = sigmoid_xla(SUBrn(__ldg(obj + anchor), bs));
        float comb = MULrn(so, bestS);
        g_score[anchor] = (comb >= 0.25f) ? comb : 0.0f;
        g_cls[anchor]   = bestI;
    }
}

// ---------------- Kernel 3: per-batch top-K (1024 threads / block) ----------
__global__ void __launch_bounds__(1024) topk_kernel(
        const float4* __restrict__ boxes, float* __restrict__ out) {
    __shared__ uint32_t skey[NA];
    __shared__ unsigned long long cand[1024];
    __shared__ uint32_t hist[256];
    __shared__ uint32_t scanb[256];
    __shared__ int s_digit, s_rem, s_cnt, s_valid;

    int b = blockIdx.x;
    int tid = threadIdx.x;
    const float* sc = g_score + (size_t)b * NA;

    if (tid == 0) { s_valid = 0; s_cnt = 0; }
    __syncthreads();

    int vc = 0;
    for (int i = tid; i < NA; i += 1024) {
        uint32_t k = __float_as_uint(sc[i]);
        skey[i] = k;
        vc += (k != 0);
    }
#pragma unroll
    for (int off = 16; off; off >>= 1) vc += __shfl_down_sync(0xffffffffu, vc, off);
    if ((tid & 31) == 0 && vc) atomicAdd(&s_valid, vc);

    // zero this batch's output region (scatter overwrites valid ranks later)
    float* ob = out;
    float* os = out + (size_t)BATCH * KTOP * 4;
    float* oc = os + (size_t)BATCH * KTOP;
    float* ou = oc + (size_t)BATCH * KTOP;
    float* ov = ou + (size_t)BATCH * KTOP;
    for (int k = tid; k < KTOP; k += 1024) {
        ((float4*)ob)[(size_t)b * KTOP + k] = make_float4(0.f, 0.f, 0.f, 0.f);
        os[(size_t)b * KTOP + k] = 0.f;
        oc[(size_t)b * KTOP + k] = 0.f;
        ou[(size_t)b * KTOP + k] = 0.f;
        ov[(size_t)b * KTOP + k] = 0.f;
    }
    __syncthreads();

    int Kv = min(s_valid, KTOP);

    uint32_t prefix = 0;
    int remaining = Kv;
    if (Kv > 0) {
        for (int shift = 24; shift >= 0; shift -= 8) {
            if (tid < 256) hist[tid] = 0;
            __syncthreads();
            uint32_t hm = (shift == 24) ? 0u : (0xFFFFFFFFu << (shift + 8));
            for (int i = tid; i < NA; i += 1024) {
                uint32_t k = skey[i];
                if (k && (k & hm) == prefix) atomicAdd(&hist[(k >> shift) & 0xFF], 1);
            }
            __syncthreads();
            if (tid < 256) scanb[tid] = hist[tid];
            __syncthreads();
            // suffix-inclusive scan: scanb[d] = sum_{d'>=d} hist[d']
#pragma unroll
            for (int off = 1; off < 256; off <<= 1) {
                uint32_t t = 0;
                if (tid < 256 && tid + off < 256) t = scanb[tid + off];
                __syncthreads();
                if (tid < 256) scanb[tid] += t;
                __syncthreads();
            }
            if (tid < 256) {
                uint32_t S  = scanb[tid];
                uint32_t Sn = (tid < 255) ? scanb[tid + 1] : 0;
                if (S >= (uint32_t)remaining && Sn < (uint32_t)remaining) {
                    s_digit = tid;
                    s_rem   = remaining - (int)Sn;
                }
            }
            __syncthreads();
            prefix |= ((uint32_t)s_digit) << shift;
            remaining = s_rem;
            __syncthreads();
        }

        // gather candidates: all keys >= exact rank-Kv pivot (ties included)
        for (int i = tid; i < NA; i += 1024) {
            uint32_t k = skey[i];
            if (k >= prefix && k != 0) {
                int p = atomicAdd(&s_cnt, 1);
                if (p < 1024)
                    cand[p] = ((unsigned long long)k << 32) | (uint32_t)(~(uint32_t)i);
            }
        }
    }
    __syncthreads();

    // rank-by-counting scatter (composite: equal keys -> lower index ranks first)
    int n = min(s_cnt, 1024);
    if (tid < n) {
        unsigned long long my = cand[tid];
        int rank = 0;
        for (int j = 0; j < n; j++) rank += (cand[j] > my);
        if (rank < Kv) {
            uint32_t key = (uint32_t)(my >> 32);
            int ai = (int)(~(uint32_t)my);
            int gi = b * NA + ai;
            ((float4*)ob)[(size_t)b * KTOP + rank] = boxes[gi];
            os[(size_t)b * KTOP + rank] = __uint_as_float(key);
            oc[(size_t)b * KTOP + rank] = (float)g_cls[gi];
            ou[(size_t)b * KTOP + rank] = g_beta[gi];
            ov[(size_t)b * KTOP + rank] = 1.0f;
        }
    }
}

extern "C" void kernel_launch(void* const* d_in, const int* in_sizes, int n_in,
                              void* d_out, int out_size) {
    const float* boxes = nullptr;
    const float* obj   = nullptr;
    const float* cls   = nullptr;
    const float* field = nullptr;
    for (int i = 0; i < n_in; i++) {
        int s = in_sizes[i];
        if      (s == BATCH * NA * 4)      boxes = (const float*)d_in[i];
        else if (s == BATCH * NA)          obj   = (const float*)d_in[i];
        else if (s == BATCH * NA * NC)     cls   = (const float*)d_in[i];
        else if (s == BATCH * HF_ * WF_)   field = (const float*)d_in[i];
    }
    pool_kernel<<<(BATCH * NA) / 256, 256>>>((const float4*)boxes, field);
    score_kernel<<<(BATCH * NA * 4) / 256, 256>>>(obj, (const float4*)cls);
    topk_kernel<<<BATCH, 1024>>>((const float4*)boxes, (float*)d_out);
}

// round 8
// speedup vs baseline: 2.1104x; 1.2547x over previous
#include <cuda_runtime.h>
#include <stdint.h>

#define BATCH 64
#define NA    8400
#define NC    80
#define HF_   160
#define WF_   160
#define KTOP  300
#define FIELD_ELEMS (HF_ * WF_)          // 25600 floats = 102.4 KB
#define POOL_SPLIT 2                     // blocks per batch image
#define POOL_THREADS 1024
#define ANCH_PER_BLK (NA / POOL_SPLIT)   // 4200

#define MULrn(a,b) __fmul_rn((a),(b))
#define ADDrn(a,b) __fadd_rn((a),(b))
#define SUBrn(a,b) __fsub_rn((a),(b))
#define DIVrn(a,b) __fdiv_rn((a),(b))

// Scratch (allocation-free rule: __device__ globals)
__device__ float g_score[BATCH * NA];
__device__ int   g_cls[BATCH * NA];
__device__ float g_beta[BATCH * NA];

// XLA EmitFastTanh (Eigen rational), no fma contraction, clamp +-7.90531110763549805,
// passthrough for |x| < 4e-4.
__device__ __forceinline__ float tanh_xla(float x) {
    const float kMax = 7.90531110763549805f;
    float xc = fmaxf(-kMax, fminf(x, kMax));
    float x2 = MULrn(xc, xc);
    float p = -2.76076847742355e-16f;
    p = ADDrn(MULrn(x2, p),  2.00018790482477e-13f);
    p = ADDrn(MULrn(x2, p), -8.60467152213735e-11f);
    p = ADDrn(MULrn(x2, p),  5.12229709037114e-08f);
    p = ADDrn(MULrn(x2, p),  1.48572235717979e-05f);
    p = ADDrn(MULrn(x2, p),  6.37261928875436e-04f);
    p = ADDrn(MULrn(x2, p),  4.89352455891786e-03f);
    float num = MULrn(xc, p);
    float q = 1.19825839466702e-06f;
    q = ADDrn(MULrn(x2, q), 1.18534705686654e-04f);
    q = ADDrn(MULrn(x2, q), 2.26843463243900e-03f);
    q = ADDrn(MULrn(x2, q), 4.89352518554385e-03f);
    float t = DIVrn(num, q);
    return (fabsf(x) < 0.0004f) ? x : t;
}

// XLA logistic: 0.5 + 0.5 * tanh(0.5 * x)  (pow-2 scalings: exact)
__device__ __forceinline__ float sigmoid_xla(float x) {
    float th = tanh_xla(MULrn(0.5f, x));
    return ADDrn(0.5f, MULrn(0.5f, th));
}

// ---------------- Kernel 1: box pooling with smem-resident field ------------
__global__ void __launch_bounds__(POOL_THREADS) pool_kernel(
        const float4* __restrict__ boxes,
        const float*  __restrict__ field) {
    extern __shared__ float sf[];        // 25600 floats (102.4 KB)
    int b    = blockIdx.x / POOL_SPLIT;
    int half = blockIdx.x % POOL_SPLIT;
    int tid  = threadIdx.x;

    // stage field[b] into shared (float4-wide, fully coalesced)
    const float4* fsrc = (const float4*)(field + (size_t)b * FIELD_ELEMS);
    float4* fdst = (float4*)sf;
#pragma unroll
    for (int i = tid; i < FIELD_ELEMS / 4; i += POOL_THREADS)
        fdst[i] = __ldg(fsrc + i);
    __syncthreads();

    for (int a = half * ANCH_PER_BLK + tid; a < (half + 1) * ANCH_PER_BLK; a += POOL_THREADS) {
        int anchor = b * NA + a;
        float4 bx = __ldg(boxes + anchor);
        float x1 = bx.x, y1 = bx.y, x2 = bx.z, y2 = bx.w;
        float dx = SUBrn(x2, x1), dy = SUBrn(y2, y1);
        float fu[3], fv[3];
        int u0[3], u1[3], v0[3], v1[3];
#pragma unroll
        for (int j = 0; j < 3; j++) {
            // XLA simplifier: (j+0.5)/3 -> (j+0.5) * rn(1/3)
            float t  = MULrn((float)j + 0.5f, 1.0f / 3.0f);
            float xs = ADDrn(x1, MULrn(t, dx));
            float ys = ADDrn(y1, MULrn(t, dy));
            float u  = fminf(fmaxf(SUBrn(MULrn(xs, 0.25f), 0.5f), 0.0f), 159.0f);
            float vv = fminf(fmaxf(SUBrn(MULrn(ys, 0.25f), 0.5f), 0.0f), 159.0f);
            float u0f = floorf(u), v0f = floorf(vv);
            fu[j] = SUBrn(u, u0f); fv[j] = SUBrn(vv, v0f);
            u0[j] = (int)u0f; v0[j] = (int)v0f;
            u1[j] = min(u0[j] + 1, WF_ - 1);
            v1[j] = min(v0[j] + 1, HF_ - 1);
        }
        float e[9];
#pragma unroll
        for (int jy = 0; jy < 3; jy++) {
            int r0 = v0[jy] * WF_, r1 = v1[jy] * WF_;
            float wv = fv[jy], omv = SUBrn(1.0f, fv[jy]);
#pragma unroll
            for (int jx = 0; jx < 3; jx++) {
                float wu = fu[jx], omu = SUBrn(1.0f, fu[jx]);
                float f00 = sf[r0 + u0[jx]];
                float f01 = sf[r0 + u1[jx]];
                float f10 = sf[r1 + u0[jx]];
                float f11 = sf[r1 + u1[jx]];
                float t1 = MULrn(MULrn(f00, omv), omu);
                float t2 = MULrn(MULrn(f01, omv), wu);
                float t3 = MULrn(MULrn(f10, wv), omu);
                float t4 = MULrn(MULrn(f11, wv), wu);
                e[jy * 3 + jx] = ADDrn(ADDrn(ADDrn(t1, t2), t3), t4);
            }
        }
        // XLA 16-lane shfl-tree reduce order:
        float s_left  = ADDrn(ADDrn(ADDrn(e[0], e[8]), e[4]), ADDrn(e[2], e[6]));
        float s_right = ADDrn(ADDrn(e[1], e[5]), ADDrn(e[3], e[7]));
        float ssum    = ADDrn(s_left, s_right);
        float beta = MULrn(ssum, 1.0f / 9.0f);             // /9 -> * rn(1/9)
        float w = fmaxf(dx, 0.0f), h = fmaxf(dy, 0.0f);
        float area = MULrn(MULrn(w, h), 1.0f / 409600.0f); // * rn(1/409600)
        float small = (area < 0.01f) ? 1.0f : 0.0f;
        g_beta[anchor] = MULrn(beta, ADDrn(1.0f, MULrn(0.5f, small)));
    }
}

// ---------------- Kernel 2: class scan + calibration (4 threads / anchor) ---
__global__ void __launch_bounds__(256) score_kernel(
        const float*  __restrict__ obj,
        const float4* __restrict__ cls) {
    int gt = blockIdx.x * 256 + threadIdx.x;
    int anchor = gt >> 2;
    int sub = gt & 3;

    const float4* cp = cls + (size_t)anchor * (NC / 4);
    float4 v[5];
#pragma unroll
    for (int q = 0; q < 5; q++) v[q] = __ldg(cp + sub + 4 * q);

    float bs = __ldg(g_beta + anchor);   // broadcast within the 4-lane group
    float halfbs = MULrn(0.5f, bs);      // exact pow-2 scale

    // max logit across the anchor's 80 classes
    float m_loc = -3.0e38f;
#pragma unroll
    for (int q = 0; q < 5; q++)
        m_loc = fmaxf(m_loc, fmaxf(fmaxf(v[q].x, v[q].y), fmaxf(v[q].z, v[q].w)));
    float m1 = m_loc;
#pragma unroll
    for (int off = 1; off < 4; off <<= 1)
        m1 = fmaxf(m1, __shfl_xor_sync(0xffffffffu, m1, off, 4));

    // exact argmax over sigmoid(cal_cls): only plateau-window candidates
    float thrW = m1 - 3e-4f;
    float bestS = -1.0f; int bestI = 0x7fffffff;
    if (m_loc > thrW) {
#pragma unroll
        for (int q = 0; q < 5; q++) {
            float ev[4] = {v[q].x, v[q].y, v[q].z, v[q].w};
#pragma unroll
            for (int r = 0; r < 4; r++) {
                if (ev[r] > thrW) {
                    int ci = (sub + 4 * q) * 4 + r;
                    float sgv = sigmoid_xla(SUBrn(ev[r], halfbs));
                    if (sgv > bestS || (sgv == bestS && ci < bestI)) { bestS = sgv; bestI = ci; }
                }
            }
        }
    }
#pragma unroll
    for (int off = 1; off < 4; off <<= 1) {
        float os = __shfl_xor_sync(0xffffffffu, bestS, off, 4);
        int   oi = __shfl_xor_sync(0xffffffffu, bestI, off, 4);
        if (os > bestS || (os == bestS && oi < bestI)) { bestS = os; bestI = oi; }
    }

    if (sub == 0) {
        float so = sigmoid_xla(SUBrn(__ldg(obj + anchor), bs));
        float comb = MULrn(so, bestS);
        g_score[anchor] = (comb >= 0.25f) ? comb : 0.0f;
        g_cls[anchor]   = bestI;
    }
}

// ---------------- Kernel 3: per-batch top-K (1024 threads / block) ----------
__global__ void __launch_bounds__(1024) topk_kernel(
        const float4* __restrict__ boxes, float* __restrict__ out) {
    __shared__ uint32_t skey[NA];
    __shared__ unsigned long long cand[1024];
    __shared__ uint32_t hist[256];
    __shared__ uint32_t scanb[256];
    __shared__ int s_digit, s_rem, s_cnt, s_valid;

    int b = blockIdx.x;
    int tid = threadIdx.x;
    const float* sc = g_score + (size_t)b * NA;

    if (tid == 0) { s_valid = 0; s_cnt = 0; }
    __syncthreads();

    int vc = 0;
    for (int i = tid; i < NA; i += 1024) {
        uint32_t k = __float_as_uint(sc[i]);
        skey[i] = k;
        vc += (k != 0);
    }
#pragma unroll
    for (int off = 16; off; off >>= 1) vc += __shfl_down_sync(0xffffffffu, vc, off);
    if ((tid & 31) == 0 && vc) atomicAdd(&s_valid, vc);

    // zero this batch's output region (scatter overwrites valid ranks later)
    float* ob = out;
    float* os = out + (size_t)BATCH * KTOP * 4;
    float* oc = os + (size_t)BATCH * KTOP;
    float* ou = oc + (size_t)BATCH * KTOP;
    float* ov = ou + (size_t)BATCH * KTOP;
    for (int k = tid; k < KTOP; k += 1024) {
        ((float4*)ob)[(size_t)b * KTOP + k] = make_float4(0.f, 0.f, 0.f, 0.f);
        os[(size_t)b * KTOP + k] = 0.f;
        oc[(size_t)b * KTOP + k] = 0.f;
        ou[(size_t)b * KTOP + k] = 0.f;
        ov[(size_t)b * KTOP + k] = 0.f;
    }
    __syncthreads();

    int Kv = min(s_valid, KTOP);

    uint32_t prefix = 0;
    int remaining = Kv;
    if (Kv > 0) {
        for (int shift = 24; shift >= 0; shift -= 8) {
            if (tid < 256) hist[tid] = 0;
            __syncthreads();
            uint32_t hm = (shift == 24) ? 0u : (0xFFFFFFFFu << (shift + 8));
            for (int i = tid; i < NA; i += 1024) {
                uint32_t k = skey[i];
                if (k && (k & hm) == prefix) atomicAdd(&hist[(k >> shift) & 0xFF], 1);
            }
            __syncthreads();
            if (tid < 256) scanb[tid] = hist[tid];
            __syncthreads();
            // suffix-inclusive scan: scanb[d] = sum_{d'>=d} hist[d']
#pragma unroll
            for (int off = 1; off < 256; off <<= 1) {
                uint32_t t = 0;
                if (tid < 256 && tid + off < 256) t = scanb[tid + off];
                __syncthreads();
                if (tid < 256) scanb[tid] += t;
                __syncthreads();
            }
            if (tid < 256) {
                uint32_t S  = scanb[tid];
                uint32_t Sn = (tid < 255) ? scanb[tid + 1] : 0;
                if (S >= (uint32_t)remaining && Sn < (uint32_t)remaining) {
                    s_digit = tid;
                    s_rem   = remaining - (int)Sn;
                }
            }
            __syncthreads();
            prefix |= ((uint32_t)s_digit) << shift;
            remaining = s_rem;
            __syncthreads();
        }

        // gather candidates: all keys >= exact rank-Kv pivot (ties included)
        for (int i = tid; i < NA; i += 1024) {
            uint32_t k = skey[i];
            if (k >= prefix && k != 0) {
                int p = atomicAdd(&s_cnt, 1);
                if (p < 1024)
                    cand[p] = ((unsigned long long)k << 32) | (uint32_t)(~(uint32_t)i);
            }
        }
    }
    __syncthreads();

    // rank-by-counting scatter (composite: equal keys -> lower index ranks first)
    int n = min(s_cnt, 1024);
    if (tid < n) {
        unsigned long long my = cand[tid];
        int rank = 0;
        for (int j = 0; j < n; j++) rank += (cand[j] > my);
        if (rank < Kv) {
            uint32_t key = (uint32_t)(my >> 32);
            int ai = (int)(~(uint32_t)my);
            int gi = b * NA + ai;
            ((float4*)ob)[(size_t)b * KTOP + rank] = boxes[gi];
            os[(size_t)b * KTOP + rank] = __uint_as_float(key);
            oc[(size_t)b * KTOP + rank] = (float)g_cls[gi];
            ou[(size_t)b * KTOP + rank] = g_beta[gi];
            ov[(size_t)b * KTOP + rank] = 1.0f;
        }
    }
}

extern "C" void kernel_launch(void* const* d_in, const int* in_sizes, int n_in,
                              void* d_out, int out_size) {
    const float* boxes = nullptr;
    const float* obj   = nullptr;
    const float* cls   = nullptr;
    const float* field = nullptr;
    for (int i = 0; i < n_in; i++) {
        int s = in_sizes[i];
        if      (s == BATCH * NA * 4)      boxes = (const float*)d_in[i];
        else if (s == BATCH * NA)          obj   = (const float*)d_in[i];
        else if (s == BATCH * NA * NC)     cls   = (const float*)d_in[i];
        else if (s == BATCH * HF_ * WF_)   field = (const float*)d_in[i];
    }
    const int smem_bytes = FIELD_ELEMS * 4;  // 102.4 KB
    cudaFuncSetAttribute(pool_kernel, cudaFuncAttributeMaxDynamicSharedMemorySize, smem_bytes);
    pool_kernel<<<BATCH * POOL_SPLIT, POOL_THREADS, smem_bytes>>>((const float4*)boxes, field);
    score_kernel<<<(BATCH * NA * 4) / 256, 256>>>(obj, (const float4*)cls);
    topk_kernel<<<BATCH, 1024>>>((const float4*)boxes, (float*)d_out);
}